// round 3
// baseline (speedup 1.0000x reference)
#include <cuda_runtime.h>
#include <cstdint>

// Per-row mode of x[N, 64], values are exactly {0..7} (floor(U*8)).
// Mode via 8-bin histogram packed into a 64-bit register (8x8-bit fields),
// warp-shuffle reduced within 16-lane groups (one row per half-warp).
// Tie-break: ascending bin scan with strict '>' picks the smallest value,
// matching torch.mode / the reference's sorted-run argmax semantics.

static constexpr int K = 64;

__global__ __launch_bounds__(256) void mode_rows_kernel(
    const float* __restrict__ x, float* __restrict__ out, int nrows)
{
    const int gtid    = blockIdx.x * blockDim.x + threadIdx.x;
    const int warp_id = gtid >> 5;
    const int lane    = threadIdx.x & 31;

    const long long row0 = (long long)warp_id * 2;   // this warp's first row
    if (row0 >= nrows) return;

    // Warp reads 2 rows = 128 floats = 32 float4, one per lane: fully
    // coalesced 512B. Lanes 0-15 hold row0 data, lanes 16-31 hold row0+1.
    const float4* p = reinterpret_cast<const float4*>(x + row0 * K);
    float4 v = p[lane];

    // Pack 8 bin counters into 8-bit fields of a u64. Per-lane field max = 4;
    // after 16-lane reduction max = 64 < 256, so fields never carry.
    unsigned long long c = 0;
    c += 1ULL << (8 * (((int)v.x) & 7));
    c += 1ULL << (8 * (((int)v.y) & 7));
    c += 1ULL << (8 * (((int)v.z) & 7));
    c += 1ULL << (8 * (((int)v.w) & 7));

    // Butterfly reduce within each 16-lane group (masks 1,2,4,8 stay in-group).
    #pragma unroll
    for (int m = 1; m <= 8; m <<= 1)
        c += __shfl_xor_sync(0xFFFFFFFFu, c, m);

    // Lanes 0 and 16 now hold the complete histogram for their row.
    if ((lane & 15) == 0) {
        int best_bin = 0;
        int best_cnt = (int)(c & 0xFF);
        #pragma unroll
        for (int b = 1; b < 8; b++) {
            int cnt = (int)((c >> (8 * b)) & 0xFF);
            if (cnt > best_cnt) { best_cnt = cnt; best_bin = b; }
        }
        out[row0 + (lane >> 4)] = (float)best_bin;
    }
}

extern "C" void kernel_launch(void* const* d_in, const int* in_sizes, int n_in,
                              void* d_out, int out_size)
{
    const float* x  = (const float*)d_in[0];
    float* out      = (float*)d_out;
    const int nrows = in_sizes[0] / K;          // 1048576

    // 2 rows per warp -> nrows/2 warps; 8 warps (256 thr) per block.
    const int warps_needed  = (nrows + 1) / 2;
    const int blocks        = (warps_needed + 7) / 8;
    mode_rows_kernel<<<blocks, 256>>>(x, out, nrows);
}

// round 5
// speedup vs baseline: 1.0593x; 1.0593x over previous
#include <cuda_runtime.h>
#include <cstdint>

// Per-row mode of x[N, 64], values exactly {0..7}.
//
// R3 redesign: the u64 packed-counter version was ALU-issue bound
// (alu=65.8%, dram=45.5%). This version:
//   - bins via FFMA magic number: t = v*4 + 2^23  -> low mantissa = 4*bin
//     (moves the convert to the idle fma pipe; exact for v in {0..7})
//   - accumulates 8x 4-bit nibble counters in ONE u32 (per-thread max 4/field)
//   - splits to two u32 byte-field counters (even/odd bins) before the
//     16-lane butterfly reduction (field max 64 < 256, carry-free)
//   - tie-break to smallest value via ascending strict-'>' scan, matching
//     torch.mode / the reference.
// Memory pattern unchanged: one float4 per lane, 512B coalesced per warp,
// 2 rows per warp.

static constexpr int K = 64;

__global__ __launch_bounds__(256) void mode_rows_kernel(
    const float4* __restrict__ x4, float* __restrict__ out, int nrows)
{
    const int gtid    = blockIdx.x * blockDim.x + threadIdx.x;
    const int warp_id = gtid >> 5;
    const int lane    = threadIdx.x & 31;

    const int row0 = warp_id * 2;
    if (row0 >= nrows) return;

    // Warp reads 32 consecutive float4 = 128 floats = rows row0, row0+1.
    float4 v = x4[(size_t)warp_id * 32 + lane];

    const float MAGIC = 8388608.0f;  // 2^23
    unsigned n = 0, s;
    s = __float_as_uint(fmaf(v.x, 4.0f, MAGIC)) & 0xFFu; n += 1u << s;
    s = __float_as_uint(fmaf(v.y, 4.0f, MAGIC)) & 0xFFu; n += 1u << s;
    s = __float_as_uint(fmaf(v.z, 4.0f, MAGIC)) & 0xFFu; n += 1u << s;
    s = __float_as_uint(fmaf(v.w, 4.0f, MAGIC)) & 0xFFu; n += 1u << s;

    // Widen nibbles -> bytes: A holds bins {0,2,4,6}, B holds bins {1,3,5,7}.
    unsigned A = n & 0x0F0F0F0Fu;
    unsigned B = (n >> 4) & 0x0F0F0F0Fu;

    // Butterfly reduce within each 16-lane group (masks 1,2,4,8 stay in-group).
    #pragma unroll
    for (int m = 1; m <= 8; m <<= 1) {
        A += __shfl_xor_sync(0xFFFFFFFFu, A, m);
        B += __shfl_xor_sync(0xFFFFFFFFu, B, m);
    }

    // Lanes 0 and 16 hold the full 8-bin histogram for their row.
    if ((lane & 15) == 0) {
        int best_bin = 0;
        int best_cnt = (int)(A & 0xFFu);                 // bin 0
        int c;
        c = (int)( B        & 0xFFu); if (c > best_cnt) { best_cnt = c; best_bin = 1; }
        c = (int)((A >>  8) & 0xFFu); if (c > best_cnt) { best_cnt = c; best_bin = 2; }
        c = (int)((B >>  8) & 0xFFu); if (c > best_cnt) { best_cnt = c; best_bin = 3; }
        c = (int)((A >> 16) & 0xFFu); if (c > best_cnt) { best_cnt = c; best_bin = 4; }
        c = (int)((B >> 16) & 0xFFu); if (c > best_cnt) { best_cnt = c; best_bin = 5; }
        c = (int)( A >> 24        );  if (c > best_cnt) { best_cnt = c; best_bin = 6; }
        c = (int)( B >> 24        );  if (c > best_cnt) { best_cnt = c; best_bin = 7; }
        out[row0 + (lane >> 4)] = (float)best_bin;
    }
}

extern "C" void kernel_launch(void* const* d_in, const int* in_sizes, int n_in,
                              void* d_out, int out_size)
{
    const float4* x4 = (const float4*)d_in[0];
    float* out       = (float*)d_out;
    const int nrows  = in_sizes[0] / K;          // 1048576

    const int warps_needed = (nrows + 1) / 2;    // 2 rows per warp
    const int blocks       = (warps_needed + 7) / 8;  // 8 warps / block
    mode_rows_kernel<<<blocks, 256>>>(x4, out, nrows);
}

// round 6
// speedup vs baseline: 1.6741x; 1.5804x over previous
#include <cuda_runtime.h>
#include <cstdint>

// Per-row mode of x[N, 64], values exactly {0..7}.
//
// R5 redesign (issue-bound at alu=61%, DRAM=48%):
//  - 4 rows per warp (8 lanes/row), 2x LDG.128 per thread, each warp-wide
//    load covers 4 full 128B lines (perfect coalescing).
//  - 3-op binning: FFMA magic (v*4 + 2^23 -> low bits = 4*bin, exact),
//    then funnel-shift WRAP (shift = bits & 31 = 4*bin, no mask needed),
//    then IADD into a 8x4-bit nibble counter (8 elems -> field max 8 < 15).
//  - split nibbles -> two byte-field counters (even/odd bins), 3-level
//    butterfly over 8-lane groups (field max 64 < 256).
//  - SIMD argmax via vmaxu4/vcmpeq4/ffs; ascending tie-break preserved
//    (smallest bin achieving the max count), matching torch.mode.

static constexpr int K = 64;

__global__ __launch_bounds__(256) void mode_rows_kernel(
    const float4* __restrict__ x4, float* __restrict__ out, int nrows)
{
    const int warp_id = (blockIdx.x * blockDim.x + threadIdx.x) >> 5;
    const int lane    = threadIdx.x & 31;
    const int r       = lane >> 3;   // row within warp's group of 4
    const int c       = lane & 7;    // float4 column (0..7)

    const int row = warp_id * 4 + r;
    if (row >= nrows) return;

    // Row = 16 float4s (256B). Thread takes float4s c and c+8 of its row.
    // Warp load 0: 4 rows x float4s 0..7  = 4 full 128B lines.
    // Warp load 1: 4 rows x float4s 8..15 = 4 full 128B lines.
    const float4* p = x4 + ((size_t)row << 4) + c;
    const float4 v0 = p[0];
    const float4 v1 = p[8];

    const float MAGIC = 8388608.0f;  // 2^23; bits(2^23 + 4v) = 0x4B000000 | 4v
    unsigned n = 0;
    n += __funnelshift_l(0u, 1u, __float_as_uint(fmaf(v0.x, 4.0f, MAGIC)));
    n += __funnelshift_l(0u, 1u, __float_as_uint(fmaf(v0.y, 4.0f, MAGIC)));
    n += __funnelshift_l(0u, 1u, __float_as_uint(fmaf(v0.z, 4.0f, MAGIC)));
    n += __funnelshift_l(0u, 1u, __float_as_uint(fmaf(v0.w, 4.0f, MAGIC)));
    n += __funnelshift_l(0u, 1u, __float_as_uint(fmaf(v1.x, 4.0f, MAGIC)));
    n += __funnelshift_l(0u, 1u, __float_as_uint(fmaf(v1.y, 4.0f, MAGIC)));
    n += __funnelshift_l(0u, 1u, __float_as_uint(fmaf(v1.z, 4.0f, MAGIC)));
    n += __funnelshift_l(0u, 1u, __float_as_uint(fmaf(v1.w, 4.0f, MAGIC)));

    // Nibble fields -> byte fields. A: bins {0,2,4,6}, B: bins {1,3,5,7}.
    unsigned A = n & 0x0F0F0F0Fu;
    unsigned B = (n >> 4) & 0x0F0F0F0Fu;

    // Butterfly reduce within each 8-lane group (masks 1,2,4 stay in-group).
    #pragma unroll
    for (int m = 1; m <= 4; m <<= 1) {
        A += __shfl_xor_sync(0xFFFFFFFFu, A, m);
        B += __shfl_xor_sync(0xFFFFFFFFu, B, m);
    }

    // Lanes 0,8,16,24 hold the full 8-bin histogram for their row.
    if (c == 0) {
        // Max count over all 8 byte-fields.
        unsigned m = __vmaxu4(A, B);
        m = __vmaxu4(m, m >> 16);
        m = __vmaxu4(m, m >> 8);
        const unsigned maxc = m & 0xFFu;
        const unsigned bc = maxc * 0x01010101u;
        const unsigned eA = __vcmpeq4(A, bc);   // 0xFF per byte == maxc
        const unsigned eB = __vcmpeq4(B, bc);
        const int pA = __ffs(eA);               // lowest matching even bin
        const int pB = __ffs(eB);               // lowest matching odd bin
        const int binA = pA ? (((pA - 1) >> 3) << 1)       : 8;
        const int binB = pB ? ((((pB - 1) >> 3) << 1) | 1) : 8;
        out[row] = (float)min(binA, binB);
    }
}

extern "C" void kernel_launch(void* const* d_in, const int* in_sizes, int n_in,
                              void* d_out, int out_size)
{
    const float4* x4 = (const float4*)d_in[0];
    float* out       = (float*)d_out;
    const int nrows  = in_sizes[0] / K;              // 1048576

    const int warps_needed = (nrows + 3) / 4;        // 4 rows per warp
    const int blocks       = (warps_needed + 7) / 8; // 8 warps per block
    mode_rows_kernel<<<blocks, 256>>>(x4, out, nrows);
}

// round 7
// speedup vs baseline: 1.7896x; 1.0689x over previous
#include <cuda_runtime.h>
#include <cstdint>

// Per-row mode of x[N, 64], values exactly {0..7}.
//
// R6: 8 rows per warp (4 lanes/row, 4x LDG.128 per thread = 2KB/warp).
//  - FFMA magic binning (v*4 + 2^23 -> low 5 bits = 4*bin, exact) +
//    funnel-shift WRAP + IADD: 3 ops/element.
//  - Two 8x4-bit nibble accumulators (8 elems each, field max 8 <= 15),
//    also splits the dependent add chain.
//  - Byte-split & merge -> A (bins 0,2,4,6), B (bins 1,3,5,7); per-thread
//    field max 16, after 4-lane reduction max 64 < 256: carry-free.
//  - 2-level butterfly (masks 1,2) within 4-lane row groups.
//  - SIMD argmax (vmaxu4/vcmpeq4/ffs) with ascending tie-break (smallest
//    bin achieving max count), matching torch.mode.

static constexpr int K = 64;

__global__ __launch_bounds__(256) void mode_rows_kernel(
    const float4* __restrict__ x4, float* __restrict__ out, int nrows)
{
    const int warp_id = (blockIdx.x * blockDim.x + threadIdx.x) >> 5;
    const int lane    = threadIdx.x & 31;
    const int r       = lane >> 2;   // row within warp's group of 8
    const int c       = lane & 3;    // float4 slot (0..3)

    const int row = warp_id * 8 + r;
    if (row >= nrows) return;

    // Row = 16 float4s. Thread takes float4s c, c+4, c+8, c+12 of its row.
    // 4 independent LDG.128 per thread; every 32B sector fully consumed.
    const float4* p = x4 + ((size_t)row << 4) + c;
    const float4 v0 = p[0];
    const float4 v1 = p[4];
    const float4 v2 = p[8];
    const float4 v3 = p[12];

    const float MAGIC = 8388608.0f;  // 2^23; bits = 0x4B000000 | 4*bin
    unsigned n0 = 0, n1 = 0;
    n0 += __funnelshift_l(0u, 1u, __float_as_uint(fmaf(v0.x, 4.0f, MAGIC)));
    n0 += __funnelshift_l(0u, 1u, __float_as_uint(fmaf(v0.y, 4.0f, MAGIC)));
    n0 += __funnelshift_l(0u, 1u, __float_as_uint(fmaf(v0.z, 4.0f, MAGIC)));
    n0 += __funnelshift_l(0u, 1u, __float_as_uint(fmaf(v0.w, 4.0f, MAGIC)));
    n0 += __funnelshift_l(0u, 1u, __float_as_uint(fmaf(v1.x, 4.0f, MAGIC)));
    n0 += __funnelshift_l(0u, 1u, __float_as_uint(fmaf(v1.y, 4.0f, MAGIC)));
    n0 += __funnelshift_l(0u, 1u, __float_as_uint(fmaf(v1.z, 4.0f, MAGIC)));
    n0 += __funnelshift_l(0u, 1u, __float_as_uint(fmaf(v1.w, 4.0f, MAGIC)));
    n1 += __funnelshift_l(0u, 1u, __float_as_uint(fmaf(v2.x, 4.0f, MAGIC)));
    n1 += __funnelshift_l(0u, 1u, __float_as_uint(fmaf(v2.y, 4.0f, MAGIC)));
    n1 += __funnelshift_l(0u, 1u, __float_as_uint(fmaf(v2.z, 4.0f, MAGIC)));
    n1 += __funnelshift_l(0u, 1u, __float_as_uint(fmaf(v2.w, 4.0f, MAGIC)));
    n1 += __funnelshift_l(0u, 1u, __float_as_uint(fmaf(v3.x, 4.0f, MAGIC)));
    n1 += __funnelshift_l(0u, 1u, __float_as_uint(fmaf(v3.y, 4.0f, MAGIC)));
    n1 += __funnelshift_l(0u, 1u, __float_as_uint(fmaf(v3.z, 4.0f, MAGIC)));
    n1 += __funnelshift_l(0u, 1u, __float_as_uint(fmaf(v3.w, 4.0f, MAGIC)));

    // Nibble fields -> byte fields. A: bins {0,2,4,6}, B: bins {1,3,5,7}.
    // Per-thread field max 16; after 4-lane reduction max 64 < 256.
    unsigned A = (n0 & 0x0F0F0F0Fu) + (n1 & 0x0F0F0F0Fu);
    unsigned B = ((n0 >> 4) & 0x0F0F0F0Fu) + ((n1 >> 4) & 0x0F0F0F0Fu);

    // Butterfly reduce within each 4-lane group (masks 1,2 stay in-group).
    #pragma unroll
    for (int m = 1; m <= 2; m <<= 1) {
        A += __shfl_xor_sync(0xFFFFFFFFu, A, m);
        B += __shfl_xor_sync(0xFFFFFFFFu, B, m);
    }

    // Lanes with c==0 hold the full 8-bin histogram for their row.
    if (c == 0) {
        unsigned m = __vmaxu4(A, B);
        m = __vmaxu4(m, m >> 16);
        m = __vmaxu4(m, m >> 8);
        const unsigned maxc = m & 0xFFu;
        const unsigned bc = maxc * 0x01010101u;
        const unsigned eA = __vcmpeq4(A, bc);   // 0xFF per byte == maxc
        const unsigned eB = __vcmpeq4(B, bc);
        const int pA = __ffs(eA);               // lowest matching even bin
        const int pB = __ffs(eB);               // lowest matching odd bin
        const int binA = pA ? (((pA - 1) >> 3) << 1)       : 8;
        const int binB = pB ? ((((pB - 1) >> 3) << 1) | 1) : 8;
        out[row] = (float)min(binA, binB);
    }
}

extern "C" void kernel_launch(void* const* d_in, const int* in_sizes, int n_in,
                              void* d_out, int out_size)
{
    const float4* x4 = (const float4*)d_in[0];
    float* out       = (float*)d_out;
    const int nrows  = in_sizes[0] / K;               // 1048576

    const int warps_needed = (nrows + 7) / 8;         // 8 rows per warp
    const int blocks       = (warps_needed + 7) / 8;  // 8 warps per block
    mode_rows_kernel<<<blocks, 256>>>(x4, out, nrows);
}